// round 13
// baseline (speedup 1.0000x reference)
#include <cuda_runtime.h>
#include <cuda_bf16.h>

// ---------------------------------------------------------------------------
// RIMDLoss fused loss — single-kernel persistent version.
// total = recon + 0.1*lap + 0.01*drift + 0.1*arap + beta*kl
//
// R7 (WIN): block work-stealing, 171.7 -> 143.1us (CTA-spread tail confirmed).
// R9 (WIN): warp stealing + fused compose, 143.1 -> 131.6us. Profile: L1=78%
//   (wall = L1tex wavefronts), L2=67%, occ=90%. 78% < cap because WCHUNK=256
//   gave only 1.65 tickets/warp -> back half of edge phase ran ~65% utilized.
// R10: WCHUNK 256 -> 32 (14 tickets/warp; ticket-atomic rate 0.6/cyc, under
//   the single-address L2 atomic cap). Predict L1 -> ~90%, dur -> ~115us.
//   (R10 bench was a container infra failure; resubmitting unchanged.)
// ---------------------------------------------------------------------------

#define NUM_GRAPHS  64
#define NODE_BLOCKS 128
#define KL_BLOCKS   32
#define WCHUNK      32     // int4-groups (4 edges each) per warp ticket

__device__ double   g_recon;   // sum (p-t)^2 over all elements
__device__ double   g_lap;     // sum d2 over edges (== sum len^2)
__device__ double   g_len;     // sum len over edges
__device__ double   g_kl;      // sum (1 + lv - mu^2 - exp(lv))
__device__ unsigned g_ticket;  // warp work-stealing counter
__device__ unsigned g_done;    // completed-blocks counter
__device__ float    g_sumx[NUM_GRAPHS];
__device__ float    g_sumy[NUM_GRAPHS];
__device__ float    g_cnt [NUM_GRAPHS];

__device__ __forceinline__ float warpReduceF(float v) {
    #pragma unroll
    for (int o = 16; o; o >>= 1) v += __shfl_down_sync(0xffffffffu, v, o);
    return v;
}
__device__ __forceinline__ double warpReduceD(double v) {
    #pragma unroll
    for (int o = 16; o; o >>= 1) v += __shfl_down_sync(0xffffffffu, v, o);
    return v;
}

// Block-reduce a double and atomically add into *dst.
__device__ __forceinline__ void blockAtomicAddD(double v, double* dst, double* sh) {
    int lane = threadIdx.x & 31;
    int wid  = threadIdx.x >> 5;
    v = warpReduceD(v);
    if (lane == 0) sh[wid] = v;
    __syncthreads();
    int nw = (blockDim.x + 31) >> 5;
    if (wid == 0) {
        double x = (lane < nw) ? sh[lane] : 0.0;
        x = warpReduceD(x);
        if (lane == 0) atomicAdd(dst, x);
    }
    __syncthreads();
}

// ---------------------------------------------------------------------------
__global__ __launch_bounds__(256)
void mega_kernel(const float2* __restrict__ pred,
                 const float2* __restrict__ targ,
                 const int*    __restrict__ batch,
                 const float*  __restrict__ mu,
                 const float*  __restrict__ logvar,
                 const int*    __restrict__ ei,   // row 0; row 1 at ei+E
                 const int*    __restrict__ epoch_ptr,
                 float*        __restrict__ out,
                 int N, int E, int GL) {
    __shared__ double   sh[32];
    __shared__ double   shl[32];
    __shared__ unsigned s_last;
    int lane = threadIdx.x & 31;

    // ------------- prologue: role-split node / KL (overlapped with edges) ----
    if (blockIdx.x < NODE_BLOCKS) {
        int gwid   = (blockIdx.x * blockDim.x + threadIdx.x) >> 5;
        int nwarps = (NODE_BLOCKS * blockDim.x) >> 5;

        float racc = 0.f;
        for (long long base = (long long)gwid * 32; base < N; base += (long long)nwarps * 32) {
            int idx   = (int)base + lane;
            bool valid = idx < N;
            float2 p = valid ? pred[idx] : make_float2(0.f, 0.f);
            if (valid) {
                float2 t = __ldcs(&targ[idx]);
                float dx = p.x - t.x, dy = p.y - t.y;
                racc += dx * dx + dy * dy;
            }
            int g  = valid ? __ldcs(&batch[idx]) : -1;
            int g0 = __shfl_sync(0xffffffffu, g, 0);
            unsigned vm = __ballot_sync(0xffffffffu, valid);
            bool uniform = __all_sync(0xffffffffu, (!valid) || (g == g0));
            if (uniform) {
                float sx = warpReduceF(valid ? p.x : 0.f);
                float sy = warpReduceF(valid ? p.y : 0.f);
                if (lane == 0 && vm) {
                    atomicAdd(&g_sumx[g0], sx);
                    atomicAdd(&g_sumy[g0], sy);
                    atomicAdd(&g_cnt [g0], (float)__popc(vm));
                }
            } else if (valid) {   // rare: warp straddles a graph boundary
                atomicAdd(&g_sumx[g], p.x);
                atomicAdd(&g_sumy[g], p.y);
                atomicAdd(&g_cnt [g], 1.f);
            }
        }
        blockAtomicAddD((double)racc, &g_recon, sh);
    } else if (blockIdx.x < NODE_BLOCKS + KL_BLOCKS) {
        float kacc = 0.f;
        int b = blockIdx.x - NODE_BLOCKS;
        for (int i = b * blockDim.x + threadIdx.x; i < GL; i += KL_BLOCKS * blockDim.x) {
            float lv = logvar[i];
            float m  = mu[i];
            kacc += 1.0f + lv - m * m - __expf(lv);
        }
        blockAtomicAddD((double)kacc, &g_kl, sh);
    }

    // ------------- edge phase: WARP-level work-stealing, fine chunks ---------
    {
        const int* ej = ei + E;
        int E4 = E >> 2;
        const int4* ei4 = (const int4*)ei;
        const int4* ej4 = (const int4*)ej;
        unsigned nChunks = (unsigned)((E4 + WCHUNK - 1) / WCHUNK);

        float s2 = 0.f, sl = 0.f;

        while (true) {
            unsigned c;
            if (lane == 0) c = atomicAdd(&g_ticket, 1u);
            c = __shfl_sync(0xffffffffu, c, 0);
            if (c >= nChunks) break;

            int base = (int)c * WCHUNK;
            int end  = base + WCHUNK; if (end > E4) end = E4;

            for (int k = base + lane; k < end; k += 32) {
                int4 a = __ldcs(&ei4[k]);
                int4 b = __ldcs(&ej4[k]);
                float2 pa0 = __ldg(&pred[a.x]); float2 pb0 = __ldg(&pred[b.x]);
                float2 pa1 = __ldg(&pred[a.y]); float2 pb1 = __ldg(&pred[b.y]);
                float2 pa2 = __ldg(&pred[a.z]); float2 pb2 = __ldg(&pred[b.z]);
                float2 pa3 = __ldg(&pred[a.w]); float2 pb3 = __ldg(&pred[b.w]);

                float dx0 = pa0.x - pb0.x, dy0 = pa0.y - pb0.y;
                float dx1 = pa1.x - pb1.x, dy1 = pa1.y - pb1.y;
                float dx2 = pa2.x - pb2.x, dy2 = pa2.y - pb2.y;
                float dx3 = pa3.x - pb3.x, dy3 = pa3.y - pb3.y;

                float d0 = dx0 * dx0 + dy0 * dy0;
                float d1 = dx1 * dx1 + dy1 * dy1;
                float d2 = dx2 * dx2 + dy2 * dy2;
                float d3 = dx3 * dx3 + dy3 * dy3;

                s2 += (d0 + d1) + (d2 + d3);
                sl += (sqrtf(d0) + sqrtf(d1)) + (sqrtf(d2) + sqrtf(d3));
            }
        }

        // tail (E % 4 — empty for E=16M, kept for generality)
        for (int k = (E4 << 2) + (int)(blockIdx.x * blockDim.x + threadIdx.x);
             k < E; k += (int)(gridDim.x * blockDim.x)) {
            float2 pa = __ldg(&pred[ei[k]]);
            float2 pb = __ldg(&pred[ej[k]]);
            float dx = pa.x - pb.x, dy = pa.y - pb.y;
            float d = dx * dx + dy * dy;
            s2 += d;
            sl += sqrtf(d);
        }

        blockAtomicAddD((double)s2, &g_lap, sh);
        blockAtomicAddD((double)sl, &g_len, shl);
    }

    // ------------- last-block-done: compose + reset --------------------------
    if (threadIdx.x == 0) {
        __threadfence();
        unsigned old = atomicAdd(&g_done, 1u);
        s_last = (old == gridDim.x - 1) ? 1u : 0u;
    }
    __syncthreads();
    if (s_last) {
        __shared__ float shd[2];
        int wid = threadIdx.x >> 5;

        if (threadIdx.x < NUM_GRAPHS) {
            int g = threadIdx.x;
            float inv = 1.0f / g_cnt[g];
            float mx = g_sumx[g] * inv;
            float my = g_sumy[g] * inv;
            float d  = mx * mx + my * my;
            d = warpReduceF(d);
            if (lane == 0) shd[wid] = d;
        }
        __syncthreads();

        if (threadIdx.x == 0) {
            float drift = (shd[0] + shd[1]) / (float)NUM_GRAPHS;
            float kl    = -0.5f * (float)g_kl / (float)NUM_GRAPHS;

            float S2 = (float)g_lap;
            float S1 = (float)g_len;
            float fE = (float)E;
            float recon = (float)g_recon / (2.0f * (float)N);
            float lap   = S2 / fE;
            float var   = (S2 - S1 * (S1 / fE)) / (fE - 1.0f);

            int epoch = epoch_ptr ? *epoch_ptr : 5;
            float beta = (epoch < 10) ? ((float)epoch * 0.1f) : 1.0f;

            out[0] = recon + 0.1f * lap + 0.01f * drift + 0.1f * var + beta * kl;

            // reset scalar state for the next graph replay
            g_recon = 0.0; g_lap = 0.0; g_len = 0.0; g_kl = 0.0;
            g_ticket = 0u; g_done = 0u;
        }
        __syncthreads();   // all reads of g_sumx/y/cnt done above
        if (threadIdx.x < NUM_GRAPHS) {
            g_sumx[threadIdx.x] = 0.f;
            g_sumy[threadIdx.x] = 0.f;
            g_cnt [threadIdx.x] = 0.f;
        }
    }
}

// ---------------------------------------------------------------------------
extern "C" void kernel_launch(void* const* d_in, const int* in_sizes, int n_in,
                              void* d_out, int out_size) {
    const float2* pred   = (const float2*)d_in[0];
    const float2* targ   = (const float2*)d_in[1];
    const int*    eidx   = (const int*)   d_in[2];
    const int*    batch  = (const int*)   d_in[3];
    const float*  mu     = (const float*) d_in[4];
    const float*  logvar = (const float*) d_in[5];
    const int*    epoch  = (n_in >= 7) ? (const int*)d_in[6] : nullptr;
    float*        out    = (float*)d_out;

    int N  = in_sizes[0] / 2;       // nodes
    int E  = in_sizes[2] / 2;       // edges
    int GL = in_sizes[4];           // NUM_GRAPHS * LATENT

    mega_kernel<<<1184, 256>>>(pred, targ, batch, mu, logvar, eidx,
                               epoch, out, N, E, GL);
}

// round 14
// speedup vs baseline: 1.2643x; 1.2643x over previous
#include <cuda_runtime.h>
#include <cuda_bf16.h>

// ---------------------------------------------------------------------------
// RIMDLoss fused loss — single-kernel persistent version.
// total = recon + 0.1*lap + 0.01*drift + 0.1*arap + beta*kl
//
// R7  (WIN): block work-stealing, 171.7 -> 143.1us.
// R9  (WIN): warp stealing + fused compose, -> 131.6us. L1=78% (wall).
// R13 (FAIL): WCHUNK 256->32 with ONE ticket counter -> 184.5us, L1=56%.
//   Lesson: 131K tickets to a single L2 address serialize at the LTS atomic
//   ALU; every warp blocks on the dependent ticket return. Contention, not
//   granularity, was the binding constraint.
// R14: 16 DISTRIBUTED ticket counters (128B apart, disjoint chunk regions,
//   cascade to next region when drained -> stealing preserved), WCHUNK=64
//   (65K tickets, ~7/warp, per-counter rate ~0.03/cyc = uncontended).
// ---------------------------------------------------------------------------

#define NUM_GRAPHS  64
#define NODE_BLOCKS 128
#define KL_BLOCKS   32
#define WCHUNK      64     // int4-groups (4 edges each) per warp ticket
#define NCOUNT      16     // distributed ticket counters

__device__ double   g_recon;   // sum (p-t)^2 over all elements
__device__ double   g_lap;     // sum d2 over edges (== sum len^2)
__device__ double   g_len;     // sum len over edges
__device__ double   g_kl;      // sum (1 + lv - mu^2 - exp(lv))
__device__ unsigned g_ticket[NCOUNT * 32];  // one counter per 128B line
__device__ unsigned g_done;    // completed-blocks counter
__device__ float    g_sumx[NUM_GRAPHS];
__device__ float    g_sumy[NUM_GRAPHS];
__device__ float    g_cnt [NUM_GRAPHS];

__device__ __forceinline__ float warpReduceF(float v) {
    #pragma unroll
    for (int o = 16; o; o >>= 1) v += __shfl_down_sync(0xffffffffu, v, o);
    return v;
}
__device__ __forceinline__ double warpReduceD(double v) {
    #pragma unroll
    for (int o = 16; o; o >>= 1) v += __shfl_down_sync(0xffffffffu, v, o);
    return v;
}

// Block-reduce a double and atomically add into *dst.
__device__ __forceinline__ void blockAtomicAddD(double v, double* dst, double* sh) {
    int lane = threadIdx.x & 31;
    int wid  = threadIdx.x >> 5;
    v = warpReduceD(v);
    if (lane == 0) sh[wid] = v;
    __syncthreads();
    int nw = (blockDim.x + 31) >> 5;
    if (wid == 0) {
        double x = (lane < nw) ? sh[lane] : 0.0;
        x = warpReduceD(x);
        if (lane == 0) atomicAdd(dst, x);
    }
    __syncthreads();
}

// ---------------------------------------------------------------------------
__global__ __launch_bounds__(256)
void mega_kernel(const float2* __restrict__ pred,
                 const float2* __restrict__ targ,
                 const int*    __restrict__ batch,
                 const float*  __restrict__ mu,
                 const float*  __restrict__ logvar,
                 const int*    __restrict__ ei,   // row 0; row 1 at ei+E
                 const int*    __restrict__ epoch_ptr,
                 float*        __restrict__ out,
                 int N, int E, int GL) {
    __shared__ double   sh[32];
    __shared__ double   shl[32];
    __shared__ unsigned s_last;
    int lane = threadIdx.x & 31;

    // ------------- prologue: role-split node / KL (overlapped with edges) ----
    if (blockIdx.x < NODE_BLOCKS) {
        int gwid   = (blockIdx.x * blockDim.x + threadIdx.x) >> 5;
        int nwarps = (NODE_BLOCKS * blockDim.x) >> 5;

        float racc = 0.f;
        for (long long base = (long long)gwid * 32; base < N; base += (long long)nwarps * 32) {
            int idx   = (int)base + lane;
            bool valid = idx < N;
            float2 p = valid ? pred[idx] : make_float2(0.f, 0.f);
            if (valid) {
                float2 t = __ldcs(&targ[idx]);
                float dx = p.x - t.x, dy = p.y - t.y;
                racc += dx * dx + dy * dy;
            }
            int g  = valid ? __ldcs(&batch[idx]) : -1;
            int g0 = __shfl_sync(0xffffffffu, g, 0);
            unsigned vm = __ballot_sync(0xffffffffu, valid);
            bool uniform = __all_sync(0xffffffffu, (!valid) || (g == g0));
            if (uniform) {
                float sx = warpReduceF(valid ? p.x : 0.f);
                float sy = warpReduceF(valid ? p.y : 0.f);
                if (lane == 0 && vm) {
                    atomicAdd(&g_sumx[g0], sx);
                    atomicAdd(&g_sumy[g0], sy);
                    atomicAdd(&g_cnt [g0], (float)__popc(vm));
                }
            } else if (valid) {   // rare: warp straddles a graph boundary
                atomicAdd(&g_sumx[g], p.x);
                atomicAdd(&g_sumy[g], p.y);
                atomicAdd(&g_cnt [g], 1.f);
            }
        }
        blockAtomicAddD((double)racc, &g_recon, sh);
    } else if (blockIdx.x < NODE_BLOCKS + KL_BLOCKS) {
        float kacc = 0.f;
        int b = blockIdx.x - NODE_BLOCKS;
        for (int i = b * blockDim.x + threadIdx.x; i < GL; i += KL_BLOCKS * blockDim.x) {
            float lv = logvar[i];
            float m  = mu[i];
            kacc += 1.0f + lv - m * m - __expf(lv);
        }
        blockAtomicAddD((double)kacc, &g_kl, sh);
    }

    // ------------- edge phase: distributed warp-level work-stealing ----------
    {
        const int* ej = ei + E;
        int E4 = E >> 2;
        const int4* ei4 = (const int4*)ei;
        const int4* ej4 = (const int4*)ej;
        unsigned nChunks = (unsigned)((E4 + WCHUNK - 1) / WCHUNK);
        unsigned perRegion = (nChunks + NCOUNT - 1) / NCOUNT;

        float s2 = 0.f, sl = 0.f;

        int startR = (int)((blockIdx.x * 8u + (unsigned)(threadIdx.x >> 5)) % NCOUNT);
        for (int rr = 0; rr < NCOUNT; rr++) {
            int r = startR + rr; if (r >= NCOUNT) r -= NCOUNT;
            unsigned regionBase = (unsigned)r * perRegion;
            if (regionBase >= nChunks) continue;
            unsigned regionSize = nChunks - regionBase;
            if (regionSize > perRegion) regionSize = perRegion;

            while (true) {
                unsigned c;
                if (lane == 0) c = atomicAdd(&g_ticket[r * 32], 1u);
                c = __shfl_sync(0xffffffffu, c, 0);
                if (c >= regionSize) break;

                int base = (int)(regionBase + c) * WCHUNK;
                int end  = base + WCHUNK; if (end > E4) end = E4;

                for (int k = base + lane; k < end; k += 32) {
                    int4 a = __ldcs(&ei4[k]);
                    int4 b = __ldcs(&ej4[k]);
                    float2 pa0 = __ldg(&pred[a.x]); float2 pb0 = __ldg(&pred[b.x]);
                    float2 pa1 = __ldg(&pred[a.y]); float2 pb1 = __ldg(&pred[b.y]);
                    float2 pa2 = __ldg(&pred[a.z]); float2 pb2 = __ldg(&pred[b.z]);
                    float2 pa3 = __ldg(&pred[a.w]); float2 pb3 = __ldg(&pred[b.w]);

                    float dx0 = pa0.x - pb0.x, dy0 = pa0.y - pb0.y;
                    float dx1 = pa1.x - pb1.x, dy1 = pa1.y - pb1.y;
                    float dx2 = pa2.x - pb2.x, dy2 = pa2.y - pb2.y;
                    float dx3 = pa3.x - pb3.x, dy3 = pa3.y - pb3.y;

                    float d0 = dx0 * dx0 + dy0 * dy0;
                    float d1 = dx1 * dx1 + dy1 * dy1;
                    float d2 = dx2 * dx2 + dy2 * dy2;
                    float d3 = dx3 * dx3 + dy3 * dy3;

                    s2 += (d0 + d1) + (d2 + d3);
                    sl += (sqrtf(d0) + sqrtf(d1)) + (sqrtf(d2) + sqrtf(d3));
                }
            }
        }

        // tail (E % 4 — empty for E=16M, kept for generality)
        for (int k = (E4 << 2) + (int)(blockIdx.x * blockDim.x + threadIdx.x);
             k < E; k += (int)(gridDim.x * blockDim.x)) {
            float2 pa = __ldg(&pred[ei[k]]);
            float2 pb = __ldg(&pred[ej[k]]);
            float dx = pa.x - pb.x, dy = pa.y - pb.y;
            float d = dx * dx + dy * dy;
            s2 += d;
            sl += sqrtf(d);
        }

        blockAtomicAddD((double)s2, &g_lap, sh);
        blockAtomicAddD((double)sl, &g_len, shl);
    }

    // ------------- last-block-done: compose + reset --------------------------
    if (threadIdx.x == 0) {
        __threadfence();
        unsigned old = atomicAdd(&g_done, 1u);
        s_last = (old == gridDim.x - 1) ? 1u : 0u;
    }
    __syncthreads();
    if (s_last) {
        __shared__ float shd[2];
        int wid = threadIdx.x >> 5;

        if (threadIdx.x < NUM_GRAPHS) {
            int g = threadIdx.x;
            float inv = 1.0f / g_cnt[g];
            float mx = g_sumx[g] * inv;
            float my = g_sumy[g] * inv;
            float d  = mx * mx + my * my;
            d = warpReduceF(d);
            if (lane == 0) shd[wid] = d;
        }
        __syncthreads();

        if (threadIdx.x == 0) {
            float drift = (shd[0] + shd[1]) / (float)NUM_GRAPHS;
            float kl    = -0.5f * (float)g_kl / (float)NUM_GRAPHS;

            float S2 = (float)g_lap;
            float S1 = (float)g_len;
            float fE = (float)E;
            float recon = (float)g_recon / (2.0f * (float)N);
            float lap   = S2 / fE;
            float var   = (S2 - S1 * (S1 / fE)) / (fE - 1.0f);

            int epoch = epoch_ptr ? *epoch_ptr : 5;
            float beta = (epoch < 10) ? ((float)epoch * 0.1f) : 1.0f;

            out[0] = recon + 0.1f * lap + 0.01f * drift + 0.1f * var + beta * kl;

            // reset scalar state for the next graph replay
            g_recon = 0.0; g_lap = 0.0; g_len = 0.0; g_kl = 0.0;
            g_done = 0u;
        }
        __syncthreads();   // all reads of g_sumx/y/cnt done above
        if (threadIdx.x < NUM_GRAPHS) {
            g_sumx[threadIdx.x] = 0.f;
            g_sumy[threadIdx.x] = 0.f;
            g_cnt [threadIdx.x] = 0.f;
        }
        if (threadIdx.x < NCOUNT) {
            g_ticket[threadIdx.x * 32] = 0u;
        }
    }
}

// ---------------------------------------------------------------------------
extern "C" void kernel_launch(void* const* d_in, const int* in_sizes, int n_in,
                              void* d_out, int out_size) {
    const float2* pred   = (const float2*)d_in[0];
    const float2* targ   = (const float2*)d_in[1];
    const int*    eidx   = (const int*)   d_in[2];
    const int*    batch  = (const int*)   d_in[3];
    const float*  mu     = (const float*) d_in[4];
    const float*  logvar = (const float*) d_in[5];
    const int*    epoch  = (n_in >= 7) ? (const int*)d_in[6] : nullptr;
    float*        out    = (float*)d_out;

    int N  = in_sizes[0] / 2;       // nodes
    int E  = in_sizes[2] / 2;       // edges
    int GL = in_sizes[4];           // NUM_GRAPHS * LATENT

    mega_kernel<<<1184, 256>>>(pred, targ, batch, mu, logvar, eidx,
                               epoch, out, N, E, GL);
}